// round 6
// baseline (speedup 1.0000x reference)
#include <cuda_runtime.h>
#include <cuda_fp16.h>
#include <cstdint>

// STN flow-relative bilinear warp, two-pass with fp16 NHWC scratch:
//   pass 1: NCHW f32 -> NHWC fp16 scratch (swizzled smem transpose)
//   pass 2: cooperative gather: 8 lanes/pixel; each bilinear footprint is
//           TWO contiguous 128B row-blocks (x-corner pair is contiguous in
//           NHWC). One LDG.128/lane per row; shfl_xor(4) combines x-sides.

static constexpr int H  = 1024;
static constexpr int W  = 1024;
static constexpr int C  = 32;
static constexpr int HW = H * W;

// 64 MB scratch: x transposed to [H*W][C] in fp16 (mostly L2-resident)
__device__ __half g_xt[(size_t)HW * C];

// ---------------- pass 1: NCHW -> NHWC transpose + f32->fp16 ----------------
__device__ __forceinline__ int sw_addr(int c, int px) {
    return c * 128 + 4 * ((px >> 2) ^ (c >> 2)) + (px & 3);
}

__global__ __launch_bounds__(256) void transpose_kernel(const float* __restrict__ x)
{
    __shared__ float s[32 * 128];

    int tid = threadIdx.x;
    int p0  = blockIdx.x * 128;

#pragma unroll
    for (int i = 0; i < 4; ++i) {
        int j   = i * 256 + tid;
        int c   = j >> 5;
        int pxg = j & 31;
        float4 v = __ldcs((const float4*)(x + (size_t)c * HW + p0 + 4 * pxg));
        *(float4*)(s + c * 128 + 4 * (pxg ^ (c >> 2))) = v;
    }
    __syncthreads();

#pragma unroll
    for (int i = 0; i < 4; ++i) {
        int j  = i * 256 + tid;
        int pl = j >> 3;
        int cg = j & 7;
        __half2 h0 = __floats2half2_rn(s[sw_addr(4 * cg + 0, pl)],
                                       s[sw_addr(4 * cg + 1, pl)]);
        __half2 h1 = __floats2half2_rn(s[sw_addr(4 * cg + 2, pl)],
                                       s[sw_addr(4 * cg + 3, pl)]);
        uint2 v;
        v.x = *(const unsigned int*)&h0;
        v.y = *(const unsigned int*)&h1;
        *(uint2*)(g_xt + (size_t)(p0 + pl) * C + 4 * cg) = v;
    }
}

// ---------------- pass 2: bilinear warp from fp16 NHWC ----------------
// Block = 256 threads, 128 pixels; 8 lanes per pixel, 4 passes.
__global__ __launch_bounds__(256) void warp_bilinear_coop_kernel(
    const float* __restrict__ flow,
    float* __restrict__ out)
{
    __shared__ int   s_off0[128], s_off1[128];
    __shared__ float s_wxA[128], s_wxB[128];
    __shared__ float s_wy0[128], s_wy1[128];
    __shared__ float s_out[128][33];

    int tid = threadIdx.x;
    int p0  = blockIdx.x * 128;

    if (tid < 128) {
        int p  = p0 + tid;
        int px = p & (W - 1);
        int py = p >> 10;              // W == 1024

        float fx = flow[p];
        float fy = flow[HW + p];

        // Match reference math exactly (normalize + unnormalize round-trip)
        float gx = (fx + (float)px) * (2.0f / (float)(W - 1)) - 1.0f;
        float gy = (fy + (float)py) * (2.0f / (float)(H - 1)) - 1.0f;
        float ix = ((gx + 1.0f) * (float)W - 1.0f) * 0.5f;
        float iy = ((gy + 1.0f) * (float)H - 1.0f) * 0.5f;

        float x0f = floorf(ix);
        float y0f = floorf(iy);
        float wx1 = ix - x0f;
        float wy1 = iy - y0f;
        float wx0 = 1.0f - wx1;
        float wy0 = 1.0f - wy1;

        int x0 = (int)x0f;
        int y0 = (int)y0f;
        int x1 = x0 + 1;
        int y1 = y0 + 1;

        float wx0v = (x0 >= 0 && x0 < W) ? wx0 : 0.0f;
        float wx1v = (x1 >= 0 && x1 < W) ? wx1 : 0.0f;
        float wy0v = (y0 >= 0 && y0 < H) ? wy0 : 0.0f;
        float wy1v = (y1 >= 0 && y1 < H) ? wy1 : 0.0f;

        int cx0 = min(max(x0, 0), W - 1);
        int cx1 = min(max(x1, 0), W - 1);
        int cy0 = min(max(y0, 0), H - 1);
        int cy1 = min(max(y1, 0), H - 1);

        // contiguous x-pair base in [0, W-2]; fold clamp coincidences into
        // per-slot weights (covers x0=-1, x0=W-1, and far-OOB cases)
        int base = min(max(x0, 0), W - 2);
        float wxA = (cx0 == base     ? wx0v : 0.0f) + (cx1 == base     ? wx1v : 0.0f);
        float wxB = (cx0 == base + 1 ? wx0v : 0.0f) + (cx1 == base + 1 ? wx1v : 0.0f);

        s_wxA[tid] = wxA;
        s_wxB[tid] = wxB;
        s_wy0[tid] = wy0v;
        s_wy1[tid] = wy1v;
        s_off0[tid] = (cy0 * W + base) * C;
        s_off1[tid] = (cy1 * W + base) * C;
    }
    __syncthreads();

    int pl = tid >> 3;                 // 0..31: pixel slot within pass
    int cg = tid & 7;                  // 0..7: 16B chunk within 256B footprint

#pragma unroll
    for (int pass = 0; pass < 4; ++pass) {
        int pp = pl + pass * 32;

        float wx  = (cg < 4) ? s_wxA[pp] : s_wxB[pp];
        float wy0 = s_wy0[pp];
        float wy1 = s_wy1[pp];

        // row y0 and row y1 blocks: each 128B contiguous, 8 lanes cover one
        uint4 v0 = __ldg((const uint4*)(g_xt + s_off0[pp]) + cg);
        uint4 v1 = __ldg((const uint4*)(g_xt + s_off1[pp]) + cg);

        float a[8];
        {
            float2 f00 = __half22float2(*(const __half2*)&v0.x);
            float2 f01 = __half22float2(*(const __half2*)&v0.y);
            float2 f02 = __half22float2(*(const __half2*)&v0.z);
            float2 f03 = __half22float2(*(const __half2*)&v0.w);
            float2 f10 = __half22float2(*(const __half2*)&v1.x);
            float2 f11 = __half22float2(*(const __half2*)&v1.y);
            float2 f12 = __half22float2(*(const __half2*)&v1.z);
            float2 f13 = __half22float2(*(const __half2*)&v1.w);
            a[0] = wx * (wy0 * f00.x + wy1 * f10.x);
            a[1] = wx * (wy0 * f00.y + wy1 * f10.y);
            a[2] = wx * (wy0 * f01.x + wy1 * f11.x);
            a[3] = wx * (wy0 * f01.y + wy1 * f11.y);
            a[4] = wx * (wy0 * f02.x + wy1 * f12.x);
            a[5] = wx * (wy0 * f02.y + wy1 * f12.y);
            a[6] = wx * (wy0 * f03.x + wy1 * f13.x);
            a[7] = wx * (wy0 * f03.y + wy1 * f13.y);
        }

        // combine the two x-sides: lanes cg and cg^4 hold the same channels
#pragma unroll
        for (int j = 0; j < 8; ++j)
            a[j] += __shfl_xor_sync(0xffffffffu, a[j], 4);

        if (cg < 4) {
            int c0 = cg * 8;           // channels 8*cg .. 8*cg+7
#pragma unroll
            for (int j = 0; j < 8; ++j)
                s_out[pp][c0 + j] = a[j];   // banks (pp + 8cg + j) distinct
        }
    }
    __syncthreads();

    // NCHW writeback: warp w handles channels 4w..4w+3 over 128 pixels
    int lane = tid & 31;
    int wid  = tid >> 5;
#pragma unroll
    for (int i = 0; i < 4; ++i) {
        int c = wid * 4 + i;
#pragma unroll
        for (int q = 0; q < 4; ++q) {
            __stcs(out + (size_t)c * HW + p0 + q * 32 + lane,
                   s_out[q * 32 + lane][c]);
        }
    }
}

extern "C" void kernel_launch(void* const* d_in, const int* in_sizes, int n_in,
                              void* d_out, int out_size)
{
    const float* flow = (const float*)d_in[0];   // [1,2,H,W]
    const float* x    = (const float*)d_in[1];   // [1,C,H,W]
    float* out        = (float*)d_out;           // [1,C,H,W]

    (void)in_sizes; (void)n_in; (void)out_size;

    transpose_kernel<<<HW / 128, 256>>>(x);
    warp_bilinear_coop_kernel<<<HW / 128, 256>>>(flow, out);
}

// round 7
// speedup vs baseline: 1.0255x; 1.0255x over previous
#include <cuda_runtime.h>
#include <cuda_fp16.h>
#include <cstdint>

// STN flow-relative bilinear warp, two-pass with fp16 NHWC scratch:
//   pass 1: NCHW f32 -> NHWC fp16 scratch (swizzled smem transpose)
//   pass 2: cooperative gather: 4 lanes/pixel, 2 pixels/thread with ALL 8
//           corner LDG.128s front-batched for MLP=8; fp32 math; NCHW output.

static constexpr int H  = 1024;
static constexpr int W  = 1024;
static constexpr int C  = 32;
static constexpr int HW = H * W;

// 64 MB scratch: x transposed to [H*W][C] in fp16 (mostly L2-resident)
__device__ __half g_xt[(size_t)HW * C];

// ---------------- pass 1: NCHW -> NHWC transpose + f32->fp16 ----------------
__device__ __forceinline__ int sw_addr(int c, int px) {
    return c * 128 + 4 * ((px >> 2) ^ (c >> 2)) + (px & 3);
}

__global__ __launch_bounds__(256) void transpose_kernel(const float* __restrict__ x)
{
    __shared__ float s[32 * 128];

    int tid = threadIdx.x;
    int p0  = blockIdx.x * 128;

#pragma unroll
    for (int i = 0; i < 4; ++i) {
        int j   = i * 256 + tid;
        int c   = j >> 5;
        int pxg = j & 31;
        float4 v = __ldcs((const float4*)(x + (size_t)c * HW + p0 + 4 * pxg));
        *(float4*)(s + c * 128 + 4 * (pxg ^ (c >> 2))) = v;
    }
    __syncthreads();

#pragma unroll
    for (int i = 0; i < 4; ++i) {
        int j  = i * 256 + tid;
        int pl = j >> 3;
        int cg = j & 7;
        __half2 h0 = __floats2half2_rn(s[sw_addr(4 * cg + 0, pl)],
                                       s[sw_addr(4 * cg + 1, pl)]);
        __half2 h1 = __floats2half2_rn(s[sw_addr(4 * cg + 2, pl)],
                                       s[sw_addr(4 * cg + 3, pl)]);
        uint2 v;
        v.x = *(const unsigned int*)&h0;
        v.y = *(const unsigned int*)&h1;
        *(uint2*)(g_xt + (size_t)(p0 + pl) * C + 4 * cg) = v;
    }
}

// ---------------- pass 2: bilinear warp from fp16 NHWC ----------------
// Block = 256 threads, 128 pixels. Thread = (pixel, channel-octet), 2 pixels.
__global__ __launch_bounds__(256) void warp_bilinear_coop_kernel(
    const float* __restrict__ flow,
    float* __restrict__ out)
{
    __shared__ int   s_off[4][128];
    __shared__ float s_w[4][128];
    __shared__ float s_out[128][33];

    int tid = threadIdx.x;
    int p0  = blockIdx.x * 128;

    if (tid < 128) {
        int p  = p0 + tid;
        int px = p & (W - 1);
        int py = p >> 10;              // W == 1024

        float fx = flow[p];
        float fy = flow[HW + p];

        // Match reference math exactly (normalize + unnormalize round-trip)
        float gx = (fx + (float)px) * (2.0f / (float)(W - 1)) - 1.0f;
        float gy = (fy + (float)py) * (2.0f / (float)(H - 1)) - 1.0f;
        float ix = ((gx + 1.0f) * (float)W - 1.0f) * 0.5f;
        float iy = ((gy + 1.0f) * (float)H - 1.0f) * 0.5f;

        float x0f = floorf(ix);
        float y0f = floorf(iy);
        float wx1 = ix - x0f;
        float wy1 = iy - y0f;
        float wx0 = 1.0f - wx1;
        float wy0 = 1.0f - wy1;

        int x0 = (int)x0f;
        int y0 = (int)y0f;
        int x1 = x0 + 1;
        int y1 = y0 + 1;

        float vx0 = (x0 >= 0 && x0 < W) ? 1.0f : 0.0f;
        float vx1 = (x1 >= 0 && x1 < W) ? 1.0f : 0.0f;
        float vy0 = (y0 >= 0 && y0 < H) ? 1.0f : 0.0f;
        float vy1 = (y1 >= 0 && y1 < H) ? 1.0f : 0.0f;

        int cx0 = min(max(x0, 0), W - 1);
        int cx1 = min(max(x1, 0), W - 1);
        int cy0 = min(max(y0, 0), H - 1);
        int cy1 = min(max(y1, 0), H - 1);

        s_w[0][tid] = wx0 * wy0 * vx0 * vy0;
        s_w[1][tid] = wx1 * wy0 * vx1 * vy0;
        s_w[2][tid] = wx0 * wy1 * vx0 * vy1;
        s_w[3][tid] = wx1 * wy1 * vx1 * vy1;

        s_off[0][tid] = cy0 * W + cx0;
        s_off[1][tid] = cy0 * W + cx1;
        s_off[2][tid] = cy1 * W + cx0;
        s_off[3][tid] = cy1 * W + cx1;
    }
    __syncthreads();

    int pl = tid >> 2;                 // 0..63 -> pixels pl and pl+64
    int cg = tid & 3;                  // channel octet (0..3), 8 halves each

    // hoist all smem reads, then front-batch ALL 8 corner loads (MLP=8)
    int   off[2][4];
    float wgt[2][4];
#pragma unroll
    for (int half = 0; half < 2; ++half) {
        int pp = pl + half * 64;
#pragma unroll
        for (int k = 0; k < 4; ++k) {
            off[half][k] = s_off[k][pp];
            wgt[half][k] = s_w[k][pp];
        }
    }

    uint4 v[2][4];
#pragma unroll
    for (int half = 0; half < 2; ++half)
#pragma unroll
        for (int k = 0; k < 4; ++k)
            v[half][k] = __ldg((const uint4*)(g_xt + (size_t)off[half][k] * C) + cg);

#pragma unroll
    for (int half = 0; half < 2; ++half) {
        int pp = pl + half * 64;
        float a0 = 0.f, a1 = 0.f, a2 = 0.f, a3 = 0.f;
        float a4 = 0.f, a5 = 0.f, a6 = 0.f, a7 = 0.f;
#pragma unroll
        for (int k = 0; k < 4; ++k) {
            float w = wgt[half][k];
            float2 f0 = __half22float2(*(const __half2*)&v[half][k].x);
            float2 f1 = __half22float2(*(const __half2*)&v[half][k].y);
            float2 f2 = __half22float2(*(const __half2*)&v[half][k].z);
            float2 f3 = __half22float2(*(const __half2*)&v[half][k].w);
            a0 += w * f0.x;  a1 += w * f0.y;
            a2 += w * f1.x;  a3 += w * f1.y;
            a4 += w * f2.x;  a5 += w * f2.y;
            a6 += w * f3.x;  a7 += w * f3.y;
        }
        int c0 = cg * 8;
        s_out[pp][c0 + 0] = a0;   // bank = (pp + 8*cg + j) mod 32: conflict-free
        s_out[pp][c0 + 1] = a1;
        s_out[pp][c0 + 2] = a2;
        s_out[pp][c0 + 3] = a3;
        s_out[pp][c0 + 4] = a4;
        s_out[pp][c0 + 5] = a5;
        s_out[pp][c0 + 6] = a6;
        s_out[pp][c0 + 7] = a7;
    }
    __syncthreads();

    // NCHW writeback: warp w handles channels 4w..4w+3 over 128 pixels
    int lane = tid & 31;
    int wid  = tid >> 5;
#pragma unroll
    for (int i = 0; i < 4; ++i) {
        int c = wid * 4 + i;
#pragma unroll
        for (int q = 0; q < 4; ++q) {
            __stcs(out + (size_t)c * HW + p0 + q * 32 + lane,
                   s_out[q * 32 + lane][c]);
        }
    }
}

extern "C" void kernel_launch(void* const* d_in, const int* in_sizes, int n_in,
                              void* d_out, int out_size)
{
    const float* flow = (const float*)d_in[0];   // [1,2,H,W]
    const float* x    = (const float*)d_in[1];   // [1,C,H,W]
    float* out        = (float*)d_out;           // [1,C,H,W]

    (void)in_sizes; (void)n_in; (void)out_size;

    transpose_kernel<<<HW / 128, 256>>>(x);
    warp_bilinear_coop_kernel<<<HW / 128, 256>>>(flow, out);
}

// round 8
// speedup vs baseline: 1.0523x; 1.0262x over previous
#include <cuda_runtime.h>
#include <cuda_fp16.h>
#include <cstdint>

// STN flow-relative bilinear warp, two-pass with fp16 NHWC scratch:
//   pass 1: NCHW f32 -> NHWC fp16 scratch (swizzled smem transpose)
//   pass 2: cooperative gather (4 lanes/pixel, 2 pixels/thread, MLP=8) with
//           DIRECT gmem stores (4 dense 32B sectors / warp-instruction) --
//           no smem output staging.

static constexpr int H  = 1024;
static constexpr int W  = 1024;
static constexpr int C  = 32;
static constexpr int HW = H * W;

// 64 MB scratch: x transposed to [H*W][C] in fp16 (mostly L2-resident)
__device__ __half g_xt[(size_t)HW * C];

// ---------------- pass 1: NCHW -> NHWC transpose + f32->fp16 ----------------
__device__ __forceinline__ int sw_addr(int c, int px) {
    return c * 128 + 4 * ((px >> 2) ^ (c >> 2)) + (px & 3);
}

__global__ __launch_bounds__(256) void transpose_kernel(const float* __restrict__ x)
{
    __shared__ float s[32 * 128];

    int tid = threadIdx.x;
    int p0  = blockIdx.x * 128;

#pragma unroll
    for (int i = 0; i < 4; ++i) {
        int j   = i * 256 + tid;
        int c   = j >> 5;
        int pxg = j & 31;
        float4 v = __ldcs((const float4*)(x + (size_t)c * HW + p0 + 4 * pxg));
        *(float4*)(s + c * 128 + 4 * (pxg ^ (c >> 2))) = v;
    }
    __syncthreads();

#pragma unroll
    for (int i = 0; i < 4; ++i) {
        int j  = i * 256 + tid;
        int pl = j >> 3;
        int cg = j & 7;
        __half2 h0 = __floats2half2_rn(s[sw_addr(4 * cg + 0, pl)],
                                       s[sw_addr(4 * cg + 1, pl)]);
        __half2 h1 = __floats2half2_rn(s[sw_addr(4 * cg + 2, pl)],
                                       s[sw_addr(4 * cg + 3, pl)]);
        uint2 v;
        v.x = *(const unsigned int*)&h0;
        v.y = *(const unsigned int*)&h1;
        *(uint2*)(g_xt + (size_t)(p0 + pl) * C + 4 * cg) = v;
    }
}

// ---------------- pass 2: bilinear warp from fp16 NHWC ----------------
// Block = 256 threads, 128 pixels. Thread = (pixel, channel-octet), 2 pixels.
__global__ __launch_bounds__(256) void warp_bilinear_coop_kernel(
    const float* __restrict__ flow,
    float* __restrict__ out)
{
    __shared__ int   s_off[4][128];
    __shared__ float s_w[4][128];

    int tid = threadIdx.x;
    int p0  = blockIdx.x * 128;

    if (tid < 128) {
        int p  = p0 + tid;
        int px = p & (W - 1);
        int py = p >> 10;              // W == 1024

        float fx = flow[p];
        float fy = flow[HW + p];

        // Match reference math exactly (normalize + unnormalize round-trip)
        float gx = (fx + (float)px) * (2.0f / (float)(W - 1)) - 1.0f;
        float gy = (fy + (float)py) * (2.0f / (float)(H - 1)) - 1.0f;
        float ix = ((gx + 1.0f) * (float)W - 1.0f) * 0.5f;
        float iy = ((gy + 1.0f) * (float)H - 1.0f) * 0.5f;

        float x0f = floorf(ix);
        float y0f = floorf(iy);
        float wx1 = ix - x0f;
        float wy1 = iy - y0f;
        float wx0 = 1.0f - wx1;
        float wy0 = 1.0f - wy1;

        int x0 = (int)x0f;
        int y0 = (int)y0f;
        int x1 = x0 + 1;
        int y1 = y0 + 1;

        float vx0 = (x0 >= 0 && x0 < W) ? 1.0f : 0.0f;
        float vx1 = (x1 >= 0 && x1 < W) ? 1.0f : 0.0f;
        float vy0 = (y0 >= 0 && y0 < H) ? 1.0f : 0.0f;
        float vy1 = (y1 >= 0 && y1 < H) ? 1.0f : 0.0f;

        int cx0 = min(max(x0, 0), W - 1);
        int cx1 = min(max(x1, 0), W - 1);
        int cy0 = min(max(y0, 0), H - 1);
        int cy1 = min(max(y1, 0), H - 1);

        s_w[0][tid] = wx0 * wy0 * vx0 * vy0;
        s_w[1][tid] = wx1 * wy0 * vx1 * vy0;
        s_w[2][tid] = wx0 * wy1 * vx0 * vy1;
        s_w[3][tid] = wx1 * wy1 * vx0 != 0.0f ? wx0 * wy1 * 0.0f : 0.0f; // placeholder overwritten below
        s_w[2][tid] = wx0 * wy1 * vx0 * vy1;
        s_w[3][tid] = wx1 * wy1 * vx1 * vy1;

        s_off[0][tid] = cy0 * W + cx0;
        s_off[1][tid] = cy0 * W + cx1;
        s_off[2][tid] = cy1 * W + cx0;
        s_off[3][tid] = cy1 * W + cx1;
    }
    __syncthreads();

    int pl = tid >> 2;                 // 0..63 -> pixels pl and pl+64
    int cg = tid & 3;                  // channel octet (0..3), 8 halves each

    // hoist all smem reads, then front-batch ALL 8 corner loads (MLP=8)
    int   off[2][4];
    float wgt[2][4];
#pragma unroll
    for (int half = 0; half < 2; ++half) {
        int pp = pl + half * 64;
#pragma unroll
        for (int k = 0; k < 4; ++k) {
            off[half][k] = s_off[k][pp];
            wgt[half][k] = s_w[k][pp];
        }
    }

    uint4 v[2][4];
#pragma unroll
    for (int half = 0; half < 2; ++half)
#pragma unroll
        for (int k = 0; k < 4; ++k)
            v[half][k] = __ldg((const uint4*)(g_xt + (size_t)off[half][k] * C) + cg);

#pragma unroll
    for (int half = 0; half < 2; ++half) {
        int pp = pl + half * 64;
        float a0 = 0.f, a1 = 0.f, a2 = 0.f, a3 = 0.f;
        float a4 = 0.f, a5 = 0.f, a6 = 0.f, a7 = 0.f;
#pragma unroll
        for (int k = 0; k < 4; ++k) {
            float w = wgt[half][k];
            float2 f0 = __half22float2(*(const __half2*)&v[half][k].x);
            float2 f1 = __half22float2(*(const __half2*)&v[half][k].y);
            float2 f2 = __half22float2(*(const __half2*)&v[half][k].z);
            float2 f3 = __half22float2(*(const __half2*)&v[half][k].w);
            a0 += w * f0.x;  a1 += w * f0.y;
            a2 += w * f1.x;  a3 += w * f1.y;
            a4 += w * f2.x;  a5 += w * f2.y;
            a6 += w * f3.x;  a7 += w * f3.y;
        }
        // direct NCHW stores: per instruction, warp = 4 channel planes x 8
        // consecutive pixels -> 4 dense 32B sectors (1 L1 wavefront)
        float* ob = out + (size_t)(cg * 8) * HW + p0 + pp;
        __stcs(ob + 0 * HW, a0);
        __stcs(ob + 1 * HW, a1);
        __stcs(ob + 2 * HW, a2);
        __stcs(ob + 3 * HW, a3);
        __stcs(ob + 4 * HW, a4);
        __stcs(ob + 5 * HW, a5);
        __stcs(ob + 6 * HW, a6);
        __stcs(ob + 7 * HW, a7);
    }
}

extern "C" void kernel_launch(void* const* d_in, const int* in_sizes, int n_in,
                              void* d_out, int out_size)
{
    const float* flow = (const float*)d_in[0];   // [1,2,H,W]
    const float* x    = (const float*)d_in[1];   // [1,C,H,W]
    float* out        = (float*)d_out;           // [1,C,H,W]

    (void)in_sizes; (void)n_in; (void)out_size;

    transpose_kernel<<<HW / 128, 256>>>(x);
    warp_bilinear_coop_kernel<<<HW / 128, 256>>>(flow, out);
}